// round 15
// baseline (speedup 1.0000x reference)
#include <cuda_runtime.h>
#include <cuda_fp16.h>
#include <cstdint>

// ---------------------------------------------------------------------------
// E=2,000,000 edges, N_S=N_T=100,000.
//   k0: zero segment-sum accumulators
//   k1: edge MLP, persistent warps, M=16 warp tile (16 edges/chunk/warp):
//       scalar layer0 in fragment layout, 2x 64x64 m16n8k16 fp16 3-term
//       hi/lo MMA layers, LN in fragment layout, exit dot via butterfly.
//       Smaller tile halves register pressure -> 4 CTAs/SM (16 warps).
//   k2: coef MLP (4->32->1); x-inputs streamed from g_xy.
//   k3: dummy (aligns ncu -s 5 capture onto the edge kernel).
// ---------------------------------------------------------------------------

#define MAX_E  2000000
#define MAX_N  100000
#define EPSLN  1e-5f
#define SLOPE  0.01f

__device__ float  g_y[MAX_E];
__device__ float2 g_xy[MAX_E];
__device__ float  g_sum_s[MAX_N];
__device__ float  g_sum_t[MAX_N];

// ---------------------------------------------------------------------------
__global__ void zero_kernel(int ns, int nt) {
    int i = blockIdx.x * blockDim.x + threadIdx.x;
    if (i < ns) g_sum_s[i] = 0.0f;
    if (i < nt) g_sum_t[i] = 0.0f;
}

__global__ void dummy_kernel() {}

// ---------------------------------------------------------------------------
__device__ __forceinline__ uint32_t smem_u32(const void* p) {
    uint32_t a;
    asm("{ .reg .u64 t; cvta.to.shared.u64 t, %1; cvt.u32.u64 %0, t; }"
        : "=r"(a) : "l"(p));
    return a;
}
__device__ __forceinline__ void lds_v2_u(uint32_t addr, uint32_t& x, uint32_t& y) {
    asm volatile("ld.shared.v2.b32 {%0,%1}, [%2];" : "=r"(x), "=r"(y) : "r"(addr));
}
__device__ __forceinline__ void sts_b32(uint32_t addr, uint32_t v) {
    asm volatile("st.shared.b32 [%0], %1;" :: "r"(addr), "r"(v));
}
__device__ __forceinline__ void mma_f16(float d[4], uint32_t a0, uint32_t a1,
                                        uint32_t a2, uint32_t a3,
                                        uint32_t b0, uint32_t b1) {
    asm volatile(
        "mma.sync.aligned.m16n8k16.row.col.f32.f16.f16.f32 "
        "{%0,%1,%2,%3}, {%4,%5,%6,%7}, {%8,%9}, {%0,%1,%2,%3};"
        : "+f"(d[0]), "+f"(d[1]), "+f"(d[2]), "+f"(d[3])
        : "r"(a0), "r"(a1), "r"(a2), "r"(a3), "r"(b0), "r"(b1));
}

__device__ __forceinline__ void split2(float x0, float x1, uint32_t& hi, uint32_t& lo) {
    __half2 h = __floats2half2_rn(x0, x1);
    hi = *reinterpret_cast<uint32_t*>(&h);
    float2 hf = __half22float2(h);
    __half2 l = __floats2half2_rn(x0 - hf.x, x1 - hf.y);
    lo = *reinterpret_cast<uint32_t*>(&l);
}

// ---------------------------------------------------------------------------
#define TB     128
#define PSB    136u            // f16x2 plane row stride bytes (34 words)
#define WPLANE 8704u           // 64 rows * 136
#define DYN_SMEM (4u * WPLANE) // 34816 B (w1h, w1l, w2h, w2l)
#define NCTA   592             // 148 SMs * 4 resident CTAs

__device__ __forceinline__ uint32_t pair_slot(int p) {
    int s = p >> 3, i = p & 7;
    return (uint32_t)(8 * s + ((i < 4) ? (2 * i) : (2 * (i - 4) + 1)));
}

// 16x64x64 layer from prebuilt A fragments; acc zeroed inside.
__device__ __forceinline__ void mma_frags16(float acc[8][4],
                                            const uint32_t Ah[4][4],
                                            const uint32_t Al[4][4],
                                            uint32_t wh, uint32_t wl, int lane) {
    int qrow = lane >> 2, qc = lane & 3;
#pragma unroll
    for (int n = 0; n < 8; n++)
#pragma unroll
        for (int f = 0; f < 4; f++) acc[n][f] = 0.f;

#pragma unroll
    for (int s = 0; s < 4; s++) {
#pragma unroll
        for (int n = 0; n < 8; n++) {
            uint32_t bh0, bh1, bl0, bl1;
            uint32_t ba = (uint32_t)(8 * n + qrow) * PSB + (uint32_t)(8 * s + 2 * qc) * 4u;
            lds_v2_u(wh + ba, bh0, bh1);
            lds_v2_u(wl + ba, bl0, bl1);
            mma_f16(acc[n], Ah[s][0], Ah[s][1], Ah[s][2], Ah[s][3], bh0, bh1);
            mma_f16(acc[n], Al[s][0], Al[s][1], Al[s][2], Al[s][3], bh0, bh1);
            mma_f16(acc[n], Ah[s][0], Ah[s][1], Ah[s][2], Ah[s][3], bl0, bl1);
        }
    }
}

// LayerNorm in D-fragment layout. Rows per thread: j=0 -> row qrow (regs 0,1),
// j=1 -> row 8+qrow (regs 2,3); stats complete via shfl-xor 1,2 over qc lanes.
__device__ __forceinline__ void frag_ln16(float acc[8][4],
                                          const float* __restrict__ lw,
                                          const float* __restrict__ lb,
                                          int lane) {
    int qc = lane & 3;
    float ls[2] = {0.f, 0.f};
    float lq[2] = {0.f, 0.f};
#pragma unroll
    for (int n = 0; n < 8; n++) {
        float t0 = acc[n][0], t1 = acc[n][1];
        float t2 = acc[n][2], t3 = acc[n][3];
        ls[0] += t0 + t1;  lq[0] += t0 * t0 + t1 * t1;
        ls[1] += t2 + t3;  lq[1] += t2 * t2 + t3 * t3;
    }
#pragma unroll
    for (int j = 0; j < 2; j++) {
        ls[j] += __shfl_xor_sync(0xffffffffu, ls[j], 1);
        lq[j] += __shfl_xor_sync(0xffffffffu, lq[j], 1);
        ls[j] += __shfl_xor_sync(0xffffffffu, ls[j], 2);
        lq[j] += __shfl_xor_sync(0xffffffffu, lq[j], 2);
    }
    float m[2], inv[2];
#pragma unroll
    for (int j = 0; j < 2; j++) {
        m[j] = ls[j] * (1.0f / 64.0f);
        float v = lq[j] * (1.0f / 64.0f) - m[j] * m[j];
        inv[j] = rsqrtf(v + EPSLN);
    }
#pragma unroll
    for (int n = 0; n < 8; n++) {
        int c0 = 8 * n + 2 * qc;
        float w0v = lw[c0], w1v = lw[c0 + 1];
        float a0v = lb[c0], a1v = lb[c0 + 1];
        acc[n][0] = (acc[n][0] - m[0]) * inv[0] * w0v + a0v;
        acc[n][1] = (acc[n][1] - m[0]) * inv[0] * w1v + a1v;
        acc[n][2] = (acc[n][2] - m[1]) * inv[1] * w0v + a0v;
        acc[n][3] = (acc[n][3] - m[1]) * inv[1] * w1v + a1v;
    }
}

// bias + LeakyReLU then LN, in fragment layout.
__device__ __forceinline__ void frag_postln16(float acc[8][4],
                                              const float* __restrict__ bias,
                                              const float* __restrict__ lw,
                                              const float* __restrict__ lb,
                                              int lane) {
    int qc = lane & 3;
#pragma unroll
    for (int n = 0; n < 8; n++) {
        int c0 = 8 * n + 2 * qc;
        float b0v = bias[c0], b1v = bias[c0 + 1];
        float t0 = acc[n][0] + b0v;
        float t1 = acc[n][1] + b1v;
        float t2 = acc[n][2] + b0v;
        float t3 = acc[n][3] + b1v;
        acc[n][0] = t0 > 0.f ? t0 : SLOPE * t0;
        acc[n][1] = t1 > 0.f ? t1 : SLOPE * t1;
        acc[n][2] = t2 > 0.f ? t2 : SLOPE * t2;
        acc[n][3] = t3 > 0.f ? t3 : SLOPE * t3;
    }
    frag_ln16(acc, lw, lb, lane);
}

// D fragment -> A fragment repack (identical thread mapping, M=16).
__device__ __forceinline__ void frags_from_acc16(const float acc[8][4],
                                                 uint32_t Ah[4][4],
                                                 uint32_t Al[4][4]) {
#pragma unroll
    for (int s = 0; s < 4; s++) {
        split2(acc[2 * s][0],     acc[2 * s][1],     Ah[s][0], Al[s][0]);
        split2(acc[2 * s][2],     acc[2 * s][3],     Ah[s][1], Al[s][1]);
        split2(acc[2 * s + 1][0], acc[2 * s + 1][1], Ah[s][2], Al[s][2]);
        split2(acc[2 * s + 1][2], acc[2 * s + 1][3], Ah[s][3], Al[s][3]);
    }
}

__global__ __launch_bounds__(TB, 4)
void edge_kernel(const float* __restrict__ x_s, const float* __restrict__ x_t,
                 const int* __restrict__ ei, const float* __restrict__ ea,
                 const float* __restrict__ w0, const float* __restrict__ b0,
                 const float* __restrict__ w1, const float* __restrict__ b1,
                 const float* __restrict__ w2, const float* __restrict__ b2,
                 const float* __restrict__ w3, const float* __restrict__ b3,
                 const float* __restrict__ lnw, const float* __restrict__ lnb,
                 int E) {
    extern __shared__ __align__(16) char dsm[];
    uint32_t dbase = smem_u32(dsm);
    uint32_t w1h = dbase;
    uint32_t w1l = w1h + WPLANE;
    uint32_t w2h = w1l + WPLANE;
    uint32_t w2l = w2h + WPLANE;

    __shared__ float w0s[192], b0s[64], b1s[64], b2s[64], w3s[64];
    __shared__ float lnws[192], lnbs[192];
    __shared__ float b3s;

    int tid = threadIdx.x;
    int warp = tid >> 5, lane = tid & 31;
    int qrow = lane >> 2, qc = lane & 3;

    // ---- one-time prologue: weights -> hi/lo f16x2 planes ----
    {
        const float2* w1v = (const float2*)w1;
        const float2* w2v = (const float2*)w2;
        for (int q = tid; q < 2048; q += TB) {
            int row = q >> 5, p = q & 31;
            uint32_t off = (uint32_t)row * PSB + pair_slot(p) * 4u;
            float2 a = w1v[q];
            uint32_t hi, lo;
            split2(a.x, a.y, hi, lo);
            sts_b32(w1h + off, hi);
            sts_b32(w1l + off, lo);
            float2 c = w2v[q];
            split2(c.x, c.y, hi, lo);
            sts_b32(w2h + off, hi);
            sts_b32(w2l + off, lo);
        }
    }
    for (int i = tid; i < 192; i += TB) { w0s[i] = w0[i]; lnws[i] = lnw[i]; lnbs[i] = lnb[i]; }
    if (tid < 64) { b0s[tid] = b0[tid]; b1s[tid] = b1[tid]; b2s[tid] = b2[tid]; w3s[tid] = w3[tid]; }
    if (tid == 0) b3s = b3[0];
    __syncthreads();

    // ---- persistent per-warp loop over 16-edge chunks ----
    int nchunks = (E + 15) >> 4;
    int gw = blockIdx.x * (TB / 32) + warp;
    int wstride = gridDim.x * (TB / 32);

    for (int ch = gw; ch < nchunks; ch += wstride) {
        int rl = lane & 15;                 // upper half lanes duplicate
        int e = ch * 16 + rl;
        int eidx = e < E ? e : (E - 1);
        int src = ei[eidx];
        int dst = ei[E + eidx];
        float xsd = x_s[src * 2 + 1];
        float xsc = x_t[dst * 2 + 1];
        float att = ea[eidx];

        if (lane < 16 && e < E) g_xy[e] = make_float2(xsd, xsc);

        // shuffle inputs to fragment rows: j=0 -> row qrow, j=1 -> row 8+qrow
        float xs2[2], xc2[2], at2[2];
#pragma unroll
        for (int j = 0; j < 2; j++) {
            int R = 8 * j + qrow;
            xs2[j] = __shfl_sync(0xffffffffu, xsd, R);
            xc2[j] = __shfl_sync(0xffffffffu, xsc, R);
            at2[j] = __shfl_sync(0xffffffffu, att, R);
        }

        // layer0 (3->64) directly in fragment layout + LeakyReLU
        float acc[8][4];
#pragma unroll
        for (int n = 0; n < 8; n++) {
            int c0 = 8 * n + 2 * qc;
#pragma unroll
            for (int j = 0; j < 2; j++) {
#pragma unroll
                for (int cc = 0; cc < 2; cc++) {
                    int c = c0 + cc;
                    float t = w0s[c * 3] * xs2[j] + w0s[c * 3 + 1] * xc2[j]
                            + w0s[c * 3 + 2] * at2[j] + b0s[c];
                    acc[n][2 * j + cc] = t > 0.f ? t : SLOPE * t;
                }
            }
        }
        frag_ln16(acc, lnws, lnbs, lane);

        uint32_t Ah[4][4], Al[4][4];
        frags_from_acc16(acc, Ah, Al);

        // ---- layer 1 ----
        mma_frags16(acc, Ah, Al, w1h, w1l, lane);
        frag_postln16(acc, b1s, lnws + 64, lnbs + 64, lane);
        frags_from_acc16(acc, Ah, Al);

        // ---- layer 2 ----
        mma_frags16(acc, Ah, Al, w2h, w2l, lane);
        frag_postln16(acc, b2s, lnws + 128, lnbs + 128, lane);

        // ---- final dot + butterfly reduce + scatter ----
        float p[2] = {0.f, 0.f};
#pragma unroll
        for (int n = 0; n < 8; n++) {
            int c0 = 8 * n + 2 * qc;
            float wa = w3s[c0], wb = w3s[c0 + 1];
            p[0] += acc[n][0] * wa + acc[n][1] * wb;
            p[1] += acc[n][2] * wa + acc[n][3] * wb;
        }
#pragma unroll
        for (int j = 0; j < 2; j++) {
            p[j] += __shfl_xor_sync(0xffffffffu, p[j], 1);
            p[j] += __shfl_xor_sync(0xffffffffu, p[j], 2);
        }
        // scatter: full-warp shuffles (uniform), then writer lanes qc<2 store.
        // qc=0 -> row qrow (p[0]); qc=1 -> row 8+qrow (p[1]).
        {
            int R = 8 * (qc & 1) + qrow;
            int src_w = __shfl_sync(0xffffffffu, src, R);
            int dst_w = __shfl_sync(0xffffffffu, dst, R);
            if (qc < 2) {
                float yv = fmaxf(p[qc] + b3s, 0.f);
                int ew = ch * 16 + R;
                if (ew < E) {
                    g_y[ew] = yv;
                    atomicAdd(&g_sum_s[src_w], yv);
                    atomicAdd(&g_sum_t[dst_w], yv);
                }
            }
        }
    }
}

// ---------------------------------------------------------------------------
__global__ __launch_bounds__(256)
void coef_kernel(const int* __restrict__ ei,
                 const float* __restrict__ fw1, const float* __restrict__ fb1,
                 const float* __restrict__ flnw, const float* __restrict__ flnb,
                 const float* __restrict__ fw2, const float* __restrict__ fb2,
                 float* __restrict__ out, int E) {
    __shared__ float fw1s[128], fb1s[32], flnws[32], flnbs[32], fw2s[32];
    __shared__ float fb2s;
    int tid = threadIdx.x;
    if (tid < 128) fw1s[tid] = fw1[tid];
    if (tid < 32) {
        fb1s[tid] = fb1[tid];
        flnws[tid] = flnw[tid];
        flnbs[tid] = flnb[tid];
        fw2s[tid] = fw2[tid];
    }
    if (tid == 0) fb2s = fb2[0];
    __syncthreads();

    int e = blockIdx.x * blockDim.x + tid;
    if (e >= E) return;

    int src = ei[e];
    int dst = ei[E + e];
    float2 xy = g_xy[e];
    float xsd = xy.x;
    float xsc = xy.y;
    float ysi = g_sum_s[src];
    float ysj = g_sum_t[dst];

    float h[32];
#pragma unroll
    for (int j = 0; j < 32; j++) {
        float t = fw1s[j * 4] * xsd + fw1s[j * 4 + 1] * ysi +
                  fw1s[j * 4 + 2] * xsc + fw1s[j * 4 + 3] * ysj + fb1s[j];
        h[j] = fmaxf(t, 0.f);
    }
    float s = 0.f;
#pragma unroll
    for (int k = 0; k < 32; k++) s += h[k];
    float m = s * (1.0f / 32.0f);
    float v = 0.f;
#pragma unroll
    for (int k = 0; k < 32; k++) { float d = h[k] - m; v += d * d; }
    v *= (1.0f / 32.0f);
    float inv = rsqrtf(v + EPSLN);

    float acc = fb2s;
#pragma unroll
    for (int k = 0; k < 32; k++) {
        float hn = (h[k] - m) * inv * flnws[k] + flnbs[k];
        acc += fw2s[k] * hn;
    }
    acc = fmaxf(acc, 0.f);
    out[e] = g_y[e] * acc;
}

// ---------------------------------------------------------------------------
extern "C" void kernel_launch(void* const* d_in, const int* in_sizes, int n_in,
                              void* d_out, int out_size) {
    const float* x_s  = (const float*)d_in[0];
    const float* x_t  = (const float*)d_in[1];
    const int*   ei   = (const int*)d_in[2];
    const float* ea   = (const float*)d_in[3];
    const float* w0   = (const float*)d_in[4];
    const float* b0   = (const float*)d_in[5];
    const float* w1   = (const float*)d_in[6];
    const float* b1   = (const float*)d_in[7];
    const float* w2   = (const float*)d_in[8];
    const float* b2   = (const float*)d_in[9];
    const float* w3   = (const float*)d_in[10];
    const float* b3   = (const float*)d_in[11];
    const float* lnw  = (const float*)d_in[12];
    const float* lnb  = (const float*)d_in[13];
    const float* fw1  = (const float*)d_in[14];
    const float* fb1  = (const float*)d_in[15];
    const float* flnw = (const float*)d_in[16];
    const float* flnb = (const float*)d_in[17];
    const float* fw2  = (const float*)d_in[18];
    const float* fb2  = (const float*)d_in[19];

    int E  = in_sizes[3];
    int NS = in_sizes[0] / 2;
    int NT = in_sizes[1] / 2;

    int nmax = NS > NT ? NS : NT;
    zero_kernel<<<(nmax + 255) / 256, 256>>>(NS, NT);

    cudaFuncSetAttribute(edge_kernel, cudaFuncAttributeMaxDynamicSharedMemorySize, DYN_SMEM);

    int ncta = (E + TB - 1) / TB;
    if (ncta > NCTA) ncta = NCTA;
    edge_kernel<<<ncta, TB, DYN_SMEM>>>(
        x_s, x_t, ei, ea, w0, b0, w1, b1, w2, b2, w3, b3, lnw, lnb, E);

    coef_kernel<<<(E + 255) / 256, 256>>>(
        ei, fw1, fb1, flnw, flnb, fw2, fb2, (float*)d_out, E);

    // period-4 launch pattern so ncu -s 5 lands on edge_kernel
    dummy_kernel<<<1, 32>>>();
}

// round 16
// speedup vs baseline: 1.3266x; 1.3266x over previous
#include <cuda_runtime.h>
#include <cuda_fp16.h>
#include <cstdint>

// ---------------------------------------------------------------------------
// E=2,000,000 edges, N_S=N_T=100,000.
//   k0: zero segment-sum accumulators
//   k1: edge MLP, persistent warps, M=32 warp tile (R11 structure):
//       scalar layer0 in fragment layout, 2x 64x64 m16n8k16 fp16 3-term
//       hi/lo MMA layers, LN in fragment layout, exit dot via butterfly.
//       R16: interleaved B planes (one LDS.128 per (s,n), stride 320B,
//       conflict-free) + bias preloaded into MMA accumulators.
//   k2: coef MLP (4->32->1); x-inputs streamed from g_xy.
//   dummies: align ncu capture (global launch index 3) onto edge_kernel.
// ---------------------------------------------------------------------------

#define MAX_E  2000000
#define MAX_N  100000
#define EPSLN  1e-5f
#define SLOPE  0.01f

__device__ float  g_y[MAX_E];
__device__ float2 g_xy[MAX_E];
__device__ float  g_sum_s[MAX_N];
__device__ float  g_sum_t[MAX_N];

// ---------------------------------------------------------------------------
__global__ void zero_kernel(int ns, int nt) {
    int i = blockIdx.x * blockDim.x + threadIdx.x;
    if (i < ns) g_sum_s[i] = 0.0f;
    if (i < nt) g_sum_t[i] = 0.0f;
}

__global__ void dummy_kernel() {}

// ---------------------------------------------------------------------------
__device__ __forceinline__ uint32_t smem_u32(const void* p) {
    uint32_t a;
    asm("{ .reg .u64 t; cvta.to.shared.u64 t, %1; cvt.u32.u64 %0, t; }"
        : "=r"(a) : "l"(p));
    return a;
}
__device__ __forceinline__ void lds_v4_u(uint32_t addr, uint32_t& x, uint32_t& y,
                                         uint32_t& z, uint32_t& w) {
    asm volatile("ld.shared.v4.b32 {%0,%1,%2,%3}, [%4];"
                 : "=r"(x), "=r"(y), "=r"(z), "=r"(w) : "r"(addr));
}
__device__ __forceinline__ void sts_b32(uint32_t addr, uint32_t v) {
    asm volatile("st.shared.b32 [%0], %1;" :: "r"(addr), "r"(v));
}
__device__ __forceinline__ void mma_f16(float d[4], uint32_t a0, uint32_t a1,
                                        uint32_t a2, uint32_t a3,
                                        uint32_t b0, uint32_t b1) {
    asm volatile(
        "mma.sync.aligned.m16n8k16.row.col.f32.f16.f16.f32 "
        "{%0,%1,%2,%3}, {%4,%5,%6,%7}, {%8,%9}, {%0,%1,%2,%3};"
        : "+f"(d[0]), "+f"(d[1]), "+f"(d[2]), "+f"(d[3])
        : "r"(a0), "r"(a1), "r"(a2), "r"(a3), "r"(b0), "r"(b1));
}

__device__ __forceinline__ void split2(float x0, float x1, uint32_t& hi, uint32_t& lo) {
    __half2 h = __floats2half2_rn(x0, x1);
    hi = *reinterpret_cast<uint32_t*>(&h);
    float2 hf = __half22float2(h);
    __half2 l = __floats2half2_rn(x0 - hf.x, x1 - hf.y);
    lo = *reinterpret_cast<uint32_t*>(&l);
}

// ---------------------------------------------------------------------------
#define TB     128
#define WRS    320u            // interleaved weight plane row stride (bytes)
#define WPLANE (64u * WRS)     // 20480 B per layer
#define DYN_SMEM (2u * WPLANE) // 40960 B (w1, w2)
#define NCTA   444             // 148 SMs * 3 resident CTAs

// 64x64 layer from prebuilt A fragments; acc preloaded with bias.
__device__ __forceinline__ void mma_frags(float acc[2][8][4],
                                          const uint32_t Ah[2][4][4],
                                          const uint32_t Al[2][4][4],
                                          uint32_t wbase,
                                          const float* __restrict__ bias,
                                          int lane) {
    int qrow = lane >> 2, qc = lane & 3;
#pragma unroll
    for (int n = 0; n < 8; n++) {
        int c0 = 8 * n + 2 * qc;
        float b0v = bias[c0], b1v = bias[c0 + 1];
#pragma unroll
        for (int mt = 0; mt < 2; mt++) {
            acc[mt][n][0] = b0v;  acc[mt][n][1] = b1v;
            acc[mt][n][2] = b0v;  acc[mt][n][3] = b1v;
        }
    }

#pragma unroll
    for (int s = 0; s < 4; s++) {
#pragma unroll
        for (int n = 0; n < 8; n++) {
            uint32_t bh0, bh1, bl0, bl1;
            uint32_t ba = (uint32_t)(8 * n + qrow) * WRS + (uint32_t)(s * 4 + qc) * 16u;
            lds_v4_u(wbase + ba, bh0, bh1, bl0, bl1);
#pragma unroll
            for (int mt = 0; mt < 2; mt++) {
                mma_f16(acc[mt][n], Ah[mt][s][0], Ah[mt][s][1], Ah[mt][s][2], Ah[mt][s][3], bh0, bh1);
                mma_f16(acc[mt][n], Al[mt][s][0], Al[mt][s][1], Al[mt][s][2], Al[mt][s][3], bh0, bh1);
                mma_f16(acc[mt][n], Ah[mt][s][0], Ah[mt][s][1], Ah[mt][s][2], Ah[mt][s][3], bl0, bl1);
            }
        }
    }
}

// LayerNorm in D-fragment layout (stats via 2 shfl-xor rounds over qc).
__device__ __forceinline__ void frag_ln(float acc[2][8][4],
                                        const float* __restrict__ lw,
                                        const float* __restrict__ lb,
                                        int lane) {
    int qc = lane & 3;
    float ls[4] = {0.f, 0.f, 0.f, 0.f};
    float lq[4] = {0.f, 0.f, 0.f, 0.f};
#pragma unroll
    for (int mt = 0; mt < 2; mt++) {
#pragma unroll
        for (int n = 0; n < 8; n++) {
            float t0 = acc[mt][n][0], t1 = acc[mt][n][1];
            float t2 = acc[mt][n][2], t3 = acc[mt][n][3];
            ls[2 * mt]     += t0 + t1;  lq[2 * mt]     += t0 * t0 + t1 * t1;
            ls[2 * mt + 1] += t2 + t3;  lq[2 * mt + 1] += t2 * t2 + t3 * t3;
        }
    }
#pragma unroll
    for (int j = 0; j < 4; j++) {
        ls[j] += __shfl_xor_sync(0xffffffffu, ls[j], 1);
        lq[j] += __shfl_xor_sync(0xffffffffu, lq[j], 1);
        ls[j] += __shfl_xor_sync(0xffffffffu, ls[j], 2);
        lq[j] += __shfl_xor_sync(0xffffffffu, lq[j], 2);
    }
    float m[4], inv[4];
#pragma unroll
    for (int j = 0; j < 4; j++) {
        m[j] = ls[j] * (1.0f / 64.0f);
        float v = lq[j] * (1.0f / 64.0f) - m[j] * m[j];
        inv[j] = rsqrtf(v + EPSLN);
    }
#pragma unroll
    for (int mt = 0; mt < 2; mt++) {
#pragma unroll
        for (int n = 0; n < 8; n++) {
            int c0 = 8 * n + 2 * qc;
            float w0v = lw[c0], w1v = lw[c0 + 1];
            float a0v = lb[c0], a1v = lb[c0 + 1];
            acc[mt][n][0] = (acc[mt][n][0] - m[2 * mt]) * inv[2 * mt] * w0v + a0v;
            acc[mt][n][1] = (acc[mt][n][1] - m[2 * mt]) * inv[2 * mt] * w1v + a1v;
            acc[mt][n][2] = (acc[mt][n][2] - m[2 * mt + 1]) * inv[2 * mt + 1] * w0v + a0v;
            acc[mt][n][3] = (acc[mt][n][3] - m[2 * mt + 1]) * inv[2 * mt + 1] * w1v + a1v;
        }
    }
}

// LeakyReLU then LN, in fragment layout (bias already in acc).
__device__ __forceinline__ void frag_postln(float acc[2][8][4],
                                            const float* __restrict__ lw,
                                            const float* __restrict__ lb,
                                            int lane) {
#pragma unroll
    for (int mt = 0; mt < 2; mt++) {
#pragma unroll
        for (int n = 0; n < 8; n++) {
#pragma unroll
            for (int f = 0; f < 4; f++) {
                float t = acc[mt][n][f];
                acc[mt][n][f] = t > 0.f ? t : SLOPE * t;
            }
        }
    }
    frag_ln(acc, lw, lb, lane);
}

// D fragment -> A fragment repack (identical thread mapping).
__device__ __forceinline__ void frags_from_acc(const float acc[2][8][4],
                                               uint32_t Ah[2][4][4],
                                               uint32_t Al[2][4][4]) {
#pragma unroll
    for (int mt = 0; mt < 2; mt++) {
#pragma unroll
        for (int s = 0; s < 4; s++) {
            split2(acc[mt][2 * s][0],     acc[mt][2 * s][1],     Ah[mt][s][0], Al[mt][s][0]);
            split2(acc[mt][2 * s][2],     acc[mt][2 * s][3],     Ah[mt][s][1], Al[mt][s][1]);
            split2(acc[mt][2 * s + 1][0], acc[mt][2 * s + 1][1], Ah[mt][s][2], Al[mt][s][2]);
            split2(acc[mt][2 * s + 1][2], acc[mt][2 * s + 1][3], Ah[mt][s][3], Al[mt][s][3]);
        }
    }
}

__global__ __launch_bounds__(TB)
void edge_kernel(const float* __restrict__ x_s, const float* __restrict__ x_t,
                 const int* __restrict__ ei, const float* __restrict__ ea,
                 const float* __restrict__ w0, const float* __restrict__ b0,
                 const float* __restrict__ w1, const float* __restrict__ b1,
                 const float* __restrict__ w2, const float* __restrict__ b2,
                 const float* __restrict__ w3, const float* __restrict__ b3,
                 const float* __restrict__ lnw, const float* __restrict__ lnb,
                 int E) {
    extern __shared__ __align__(16) char dsm[];
    uint32_t dbase = smem_u32(dsm);
    uint32_t w1b = dbase;
    uint32_t w2b = w1b + WPLANE;

    __shared__ __align__(8) float w0s[192], b0s[64], b1s[64], b2s[64], w3s[64];
    __shared__ __align__(8) float lnws[192], lnbs[192];
    __shared__ float b3s;

    int tid = threadIdx.x;
    int warp = tid >> 5, lane = tid & 31;
    int qrow = lane >> 2, qc = lane & 3;

    // ---- one-time prologue: weights -> interleaved hi/lo f16x2 planes ----
    // For each row, 16 blocks of 16B: block (s*4 + qc') holds
    // [hi(slot even), hi(slot odd), lo(slot even), lo(slot odd)] where slots
    // follow the R11 pair_slot permutation: pair p -> slot u = 8s' + v,
    // block = s'*4 + (v>>1), word (v&1) for hi, 2+(v&1) for lo.
    {
        const float2* w1v = (const float2*)w1;
        const float2* w2v = (const float2*)w2;
        for (int q = tid; q < 2048; q += TB) {
            int row = q >> 5, p = q & 31;
            int sp = p >> 3, i = p & 7;
            int v = (i < 4) ? (2 * i) : (2 * (i - 4) + 1);
            uint32_t base = (uint32_t)row * WRS + (uint32_t)(sp * 4 + (v >> 1)) * 16u;
            uint32_t hioff = base + (uint32_t)(v & 1) * 4u;
            uint32_t looff = hioff + 8u;
            float2 a = w1v[q];
            uint32_t hi, lo;
            split2(a.x, a.y, hi, lo);
            sts_b32(w1b + hioff, hi);
            sts_b32(w1b + looff, lo);
            float2 c = w2v[q];
            split2(c.x, c.y, hi, lo);
            sts_b32(w2b + hioff, hi);
            sts_b32(w2b + looff, lo);
        }
    }
    for (int i = tid; i < 192; i += TB) { w0s[i] = w0[i]; lnws[i] = lnw[i]; lnbs[i] = lnb[i]; }
    if (tid < 64) { b0s[tid] = b0[tid]; b1s[tid] = b1[tid]; b2s[tid] = b2[tid]; w3s[tid] = w3[tid]; }
    if (tid == 0) b3s = b3[0];
    __syncthreads();

    // ---- persistent per-warp loop over 32-edge chunks ----
    int nchunks = (E + 31) >> 5;
    int gw = blockIdx.x * (TB / 32) + warp;
    int wstride = gridDim.x * (TB / 32);

    for (int ch = gw; ch < nchunks; ch += wstride) {
        int e = ch * 32 + lane;
        bool active = (e < E);
        int eidx = active ? e : (E - 1);
        int src = ei[eidx];
        int dst = ei[E + eidx];
        float xsd = x_s[src * 2 + 1];
        float xsc = x_t[dst * 2 + 1];
        float att = ea[eidx];

        if (active) g_xy[e] = make_float2(xsd, xsc);

        // shuffle inputs to fragment rows: j=2*mt+half -> row 16*mt+8*half+qrow
        float xs4[4], xc4[4], at4[4];
#pragma unroll
        for (int j = 0; j < 4; j++) {
            int R = 16 * (j >> 1) + 8 * (j & 1) + qrow;
            xs4[j] = __shfl_sync(0xffffffffu, xsd, R);
            xc4[j] = __shfl_sync(0xffffffffu, xsc, R);
            at4[j] = __shfl_sync(0xffffffffu, att, R);
        }

        // layer0 (3->64) directly in fragment layout + LeakyReLU
        float acc[2][8][4];
#pragma unroll
        for (int mt = 0; mt < 2; mt++) {
#pragma unroll
            for (int n = 0; n < 8; n++) {
                int c0 = 8 * n + 2 * qc;
#pragma unroll
                for (int half = 0; half < 2; half++) {
                    int j = 2 * mt + half;
#pragma unroll
                    for (int cc = 0; cc < 2; cc++) {
                        int c = c0 + cc;
                        float t = w0s[c * 3] * xs4[j] + w0s[c * 3 + 1] * xc4[j]
                                + w0s[c * 3 + 2] * at4[j] + b0s[c];
                        acc[mt][n][2 * half + cc] = t > 0.f ? t : SLOPE * t;
                    }
                }
            }
        }
        frag_ln(acc, lnws, lnbs, lane);

        uint32_t Ah[2][4][4], Al[2][4][4];
        frags_from_acc(acc, Ah, Al);

        // ---- layer 1 ----
        mma_frags(acc, Ah, Al, w1b, b1s, lane);
        frag_postln(acc, lnws + 64, lnbs + 64, lane);
        frags_from_acc(acc, Ah, Al);

        // ---- layer 2 ----
        mma_frags(acc, Ah, Al, w2b, b2s, lane);
        frag_postln(acc, lnws + 128, lnbs + 128, lane);

        // ---- final dot + butterfly reduce + scatter ----
        float p[4] = {0.f, 0.f, 0.f, 0.f};
#pragma unroll
        for (int mt = 0; mt < 2; mt++) {
#pragma unroll
            for (int n = 0; n < 8; n++) {
                int c0 = 8 * n + 2 * qc;
                float wa = w3s[c0], wb = w3s[c0 + 1];
                p[2 * mt]     += acc[mt][n][0] * wa + acc[mt][n][1] * wb;
                p[2 * mt + 1] += acc[mt][n][2] * wa + acc[mt][n][3] * wb;
            }
        }
#pragma unroll
        for (int j = 0; j < 4; j++) {
            p[j] += __shfl_xor_sync(0xffffffffu, p[j], 1);
            p[j] += __shfl_xor_sync(0xffffffffu, p[j], 2);
        }
        int jw = qc;                                   // lane outputs row-group jw
        int R = 16 * (jw >> 1) + 8 * (jw & 1) + qrow;  // row within warp tile
        float yv = fmaxf(p[2 * (jw >> 1) + (jw & 1)] + b3s, 0.f);
        int ew = ch * 32 + R;
        int src_w = __shfl_sync(0xffffffffu, src, R);
        int dst_w = __shfl_sync(0xffffffffu, dst, R);
        if (ew < E) {
            g_y[ew] = yv;
            atomicAdd(&g_sum_s[src_w], yv);
            atomicAdd(&g_sum_t[dst_w], yv);
        }
    }
}

// ---------------------------------------------------------------------------
__global__ __launch_bounds__(256)
void coef_kernel(const int* __restrict__ ei,
                 const float* __restrict__ fw1, const float* __restrict__ fb1,
                 const float* __restrict__ flnw, const float* __restrict__ flnb,
                 const float* __restrict__ fw2, const float* __restrict__ fb2,
                 float* __restrict__ out, int E) {
    __shared__ float fw1s[128], fb1s[32], flnws[32], flnbs[32], fw2s[32];
    __shared__ float fb2s;
    int tid = threadIdx.x;
    if (tid < 128) fw1s[tid] = fw1[tid];
    if (tid < 32) {
        fb1s[tid] = fb1[tid];
        flnws[tid] = flnw[tid];
        flnbs[tid] = flnb[tid];
        fw2s[tid] = fw2[tid];
    }
    if (tid == 0) fb2s = fb2[0];
    __syncthreads();

    int e = blockIdx.x * blockDim.x + tid;
    if (e >= E) return;

    int src = ei[e];
    int dst = ei[E + e];
    float2 xy = g_xy[e];
    float xsd = xy.x;
    float xsc = xy.y;
    float ysi = g_sum_s[src];
    float ysj = g_sum_t[dst];

    float h[32];
#pragma unroll
    for (int j = 0; j < 32; j++) {
        float t = fw1s[j * 4] * xsd + fw1s[j * 4 + 1] * ysi +
                  fw1s[j * 4 + 2] * xsc + fw1s[j * 4 + 3] * ysj + fb1s[j];
        h[j] = fmaxf(t, 0.f);
    }
    float s = 0.f;
#pragma unroll
    for (int k = 0; k < 32; k++) s += h[k];
    float m = s * (1.0f / 32.0f);
    float v = 0.f;
#pragma unroll
    for (int k = 0; k < 32; k++) { float d = h[k] - m; v += d * d; }
    v *= (1.0f / 32.0f);
    float inv = rsqrtf(v + EPSLN);

    float acc = fb2s;
#pragma unroll
    for (int k = 0; k < 32; k++) {
        float hn = (h[k] - m) * inv * flnws[k] + flnbs[k];
        acc += fw2s[k] * hn;
    }
    acc = fmaxf(acc, 0.f);
    out[e] = g_y[e] * acc;
}

// ---------------------------------------------------------------------------
extern "C" void kernel_launch(void* const* d_in, const int* in_sizes, int n_in,
                              void* d_out, int out_size) {
    const float* x_s  = (const float*)d_in[0];
    const float* x_t  = (const float*)d_in[1];
    const int*   ei   = (const int*)d_in[2];
    const float* ea   = (const float*)d_in[3];
    const float* w0   = (const float*)d_in[4];
    const float* b0   = (const float*)d_in[5];
    const float* w1   = (const float*)d_in[6];
    const float* b1   = (const float*)d_in[7];
    const float* w2   = (const float*)d_in[8];
    const float* b2   = (const float*)d_in[9];
    const float* w3   = (const float*)d_in[10];
    const float* b3   = (const float*)d_in[11];
    const float* lnw  = (const float*)d_in[12];
    const float* lnb  = (const float*)d_in[13];
    const float* fw1  = (const float*)d_in[14];
    const float* fb1  = (const float*)d_in[15];
    const float* flnw = (const float*)d_in[16];
    const float* flnb = (const float*)d_in[17];
    const float* fw2  = (const float*)d_in[18];
    const float* fb2  = (const float*)d_in[19];

    int E  = in_sizes[3];
    int NS = in_sizes[0] / 2;
    int NT = in_sizes[1] / 2;

    int nmax = NS > NT ? NS : NT;
    zero_kernel<<<(nmax + 255) / 256, 256>>>(NS, NT);

    // two dummies so ncu's capture (global launch index 3) lands on edge_kernel
    dummy_kernel<<<1, 32>>>();
    dummy_kernel<<<1, 32>>>();

    cudaFuncSetAttribute(edge_kernel, cudaFuncAttributeMaxDynamicSharedMemorySize, DYN_SMEM);

    int ncta = (E + TB - 1) / TB;
    if (ncta > NCTA) ncta = NCTA;
    edge_kernel<<<ncta, TB, DYN_SMEM>>>(
        x_s, x_t, ei, ea, w0, b0, w1, b1, w2, b2, w3, b3, lnw, lnb, E);

    coef_kernel<<<(E + 255) / 256, 256>>>(
        ei, fw1, fb1, flnw, flnb, fw2, fb2, (float*)d_out, E);
}

// round 17
// speedup vs baseline: 1.4907x; 1.1238x over previous
#include <cuda_runtime.h>
#include <cuda_fp16.h>
#include <cstdint>

// ---------------------------------------------------------------------------
// E=2,000,000 edges, N_S=N_T=100,000.
//   k0: zero segment-sum accumulators
//   k1: edge MLP, persistent warps, M=32 warp tile, interleaved B planes
//       (LDS.128), bias preloaded into MMA accumulators.
//       R17: __launch_bounds__(128,3) caps regs at 168 -> 3 CTAs/SM
//       (R16 ncu showed 170 regs -> only 2 CTAs resident, occ 10.3%).
//   k2: coef MLP (4->32->1); x-inputs streamed from g_xy.
//   dummies: align ncu capture (global launch index 3) onto edge_kernel.
// ---------------------------------------------------------------------------

#define MAX_E  2000000
#define MAX_N  100000
#define EPSLN  1e-5f
#define SLOPE  0.01f

__device__ float  g_y[MAX_E];
__device__ float2 g_xy[MAX_E];
__device__ float  g_sum_s[MAX_N];
__device__ float  g_sum_t[MAX_N];

// ---------------------------------------------------------------------------
__global__ void zero_kernel(int ns, int nt) {
    int i = blockIdx.x * blockDim.x + threadIdx.x;
    if (i < ns) g_sum_s[i] = 0.0f;
    if (i < nt) g_sum_t[i] = 0.0f;
}

__global__ void dummy_kernel() {}

// ---------------------------------------------------------------------------
__device__ __forceinline__ uint32_t smem_u32(const void* p) {
    uint32_t a;
    asm("{ .reg .u64 t; cvta.to.shared.u64 t, %1; cvt.u32.u64 %0, t; }"
        : "=r"(a) : "l"(p));
    return a;
}
__device__ __forceinline__ void lds_v4_u(uint32_t addr, uint32_t& x, uint32_t& y,
                                         uint32_t& z, uint32_t& w) {
    asm volatile("ld.shared.v4.b32 {%0,%1,%2,%3}, [%4];"
                 : "=r"(x), "=r"(y), "=r"(z), "=r"(w) : "r"(addr));
}
__device__ __forceinline__ void sts_b32(uint32_t addr, uint32_t v) {
    asm volatile("st.shared.b32 [%0], %1;" :: "r"(addr), "r"(v));
}
__device__ __forceinline__ void mma_f16(float d[4], uint32_t a0, uint32_t a1,
                                        uint32_t a2, uint32_t a3,
                                        uint32_t b0, uint32_t b1) {
    asm volatile(
        "mma.sync.aligned.m16n8k16.row.col.f32.f16.f16.f32 "
        "{%0,%1,%2,%3}, {%4,%5,%6,%7}, {%8,%9}, {%0,%1,%2,%3};"
        : "+f"(d[0]), "+f"(d[1]), "+f"(d[2]), "+f"(d[3])
        : "r"(a0), "r"(a1), "r"(a2), "r"(a3), "r"(b0), "r"(b1));
}

__device__ __forceinline__ void split2(float x0, float x1, uint32_t& hi, uint32_t& lo) {
    __half2 h = __floats2half2_rn(x0, x1);
    hi = *reinterpret_cast<uint32_t*>(&h);
    float2 hf = __half22float2(h);
    __half2 l = __floats2half2_rn(x0 - hf.x, x1 - hf.y);
    lo = *reinterpret_cast<uint32_t*>(&l);
}

// ---------------------------------------------------------------------------
#define TB     128
#define WRS    320u            // interleaved weight plane row stride (bytes)
#define WPLANE (64u * WRS)     // 20480 B per layer
#define DYN_SMEM (2u * WPLANE) // 40960 B (w1, w2)
#define NCTA   444             // 148 SMs * 3 resident CTAs

// 64x64 layer from prebuilt A fragments; acc preloaded with bias.
__device__ __forceinline__ void mma_frags(float acc[2][8][4],
                                          const uint32_t Ah[2][4][4],
                                          const uint32_t Al[2][4][4],
                                          uint32_t wbase,
                                          const float* __restrict__ bias,
                                          int lane) {
    int qrow = lane >> 2, qc = lane & 3;
#pragma unroll
    for (int n = 0; n < 8; n++) {
        int c0 = 8 * n + 2 * qc;
        float b0v = bias[c0], b1v = bias[c0 + 1];
#pragma unroll
        for (int mt = 0; mt < 2; mt++) {
            acc[mt][n][0] = b0v;  acc[mt][n][1] = b1v;
            acc[mt][n][2] = b0v;  acc[mt][n][3] = b1v;
        }
    }

#pragma unroll
    for (int s = 0; s < 4; s++) {
#pragma unroll
        for (int n = 0; n < 8; n++) {
            uint32_t bh0, bh1, bl0, bl1;
            uint32_t ba = (uint32_t)(8 * n + qrow) * WRS + (uint32_t)(s * 4 + qc) * 16u;
            lds_v4_u(wbase + ba, bh0, bh1, bl0, bl1);
#pragma unroll
            for (int mt = 0; mt < 2; mt++) {
                mma_f16(acc[mt][n], Ah[mt][s][0], Ah[mt][s][1], Ah[mt][s][2], Ah[mt][s][3], bh0, bh1);
                mma_f16(acc[mt][n], Al[mt][s][0], Al[mt][s][1], Al[mt][s][2], Al[mt][s][3], bh0, bh1);
                mma_f16(acc[mt][n], Ah[mt][s][0], Ah[mt][s][1], Ah[mt][s][2], Ah[mt][s][3], bl0, bl1);
            }
        }
    }
}

// LayerNorm in D-fragment layout (stats via 2 shfl-xor rounds over qc).
__device__ __forceinline__ void frag_ln(float acc[2][8][4],
                                        const float* __restrict__ lw,
                                        const float* __restrict__ lb,
                                        int lane) {
    int qc = lane & 3;
    float ls[4] = {0.f, 0.f, 0.f, 0.f};
    float lq[4] = {0.f, 0.f, 0.f, 0.f};
#pragma unroll
    for (int mt = 0; mt < 2; mt++) {
#pragma unroll
        for (int n = 0; n < 8; n++) {
            float t0 = acc[mt][n][0], t1 = acc[mt][n][1];
            float t2 = acc[mt][n][2], t3 = acc[mt][n][3];
            ls[2 * mt]     += t0 + t1;  lq[2 * mt]     += t0 * t0 + t1 * t1;
            ls[2 * mt + 1] += t2 + t3;  lq[2 * mt + 1] += t2 * t2 + t3 * t3;
        }
    }
#pragma unroll
    for (int j = 0; j < 4; j++) {
        ls[j] += __shfl_xor_sync(0xffffffffu, ls[j], 1);
        lq[j] += __shfl_xor_sync(0xffffffffu, lq[j], 1);
        ls[j] += __shfl_xor_sync(0xffffffffu, ls[j], 2);
        lq[j] += __shfl_xor_sync(0xffffffffu, lq[j], 2);
    }
    float m[4], inv[4];
#pragma unroll
    for (int j = 0; j < 4; j++) {
        m[j] = ls[j] * (1.0f / 64.0f);
        float v = lq[j] * (1.0f / 64.0f) - m[j] * m[j];
        inv[j] = rsqrtf(v + EPSLN);
    }
#pragma unroll
    for (int mt = 0; mt < 2; mt++) {
#pragma unroll
        for (int n = 0; n < 8; n++) {
            int c0 = 8 * n + 2 * qc;
            float w0v = lw[c0], w1v = lw[c0 + 1];
            float a0v = lb[c0], a1v = lb[c0 + 1];
            acc[mt][n][0] = (acc[mt][n][0] - m[2 * mt]) * inv[2 * mt] * w0v + a0v;
            acc[mt][n][1] = (acc[mt][n][1] - m[2 * mt]) * inv[2 * mt] * w1v + a1v;
            acc[mt][n][2] = (acc[mt][n][2] - m[2 * mt + 1]) * inv[2 * mt + 1] * w0v + a0v;
            acc[mt][n][3] = (acc[mt][n][3] - m[2 * mt + 1]) * inv[2 * mt + 1] * w1v + a1v;
        }
    }
}

// LeakyReLU then LN, in fragment layout (bias already in acc).
__device__ __forceinline__ void frag_postln(float acc[2][8][4],
                                            const float* __restrict__ lw,
                                            const float* __restrict__ lb,
                                            int lane) {
#pragma unroll
    for (int mt = 0; mt < 2; mt++) {
#pragma unroll
        for (int n = 0; n < 8; n++) {
#pragma unroll
            for (int f = 0; f < 4; f++) {
                float t = acc[mt][n][f];
                acc[mt][n][f] = t > 0.f ? t : SLOPE * t;
            }
        }
    }
    frag_ln(acc, lw, lb, lane);
}

// D fragment -> A fragment repack (identical thread mapping).
__device__ __forceinline__ void frags_from_acc(const float acc[2][8][4],
                                               uint32_t Ah[2][4][4],
                                               uint32_t Al[2][4][4]) {
#pragma unroll
    for (int mt = 0; mt < 2; mt++) {
#pragma unroll
        for (int s = 0; s < 4; s++) {
            split2(acc[mt][2 * s][0],     acc[mt][2 * s][1],     Ah[mt][s][0], Al[mt][s][0]);
            split2(acc[mt][2 * s][2],     acc[mt][2 * s][3],     Ah[mt][s][1], Al[mt][s][1]);
            split2(acc[mt][2 * s + 1][0], acc[mt][2 * s + 1][1], Ah[mt][s][2], Al[mt][s][2]);
            split2(acc[mt][2 * s + 1][2], acc[mt][2 * s + 1][3], Ah[mt][s][3], Al[mt][s][3]);
        }
    }
}

__global__ __launch_bounds__(TB, 3)
void edge_kernel(const float* __restrict__ x_s, const float* __restrict__ x_t,
                 const int* __restrict__ ei, const float* __restrict__ ea,
                 const float* __restrict__ w0, const float* __restrict__ b0,
                 const float* __restrict__ w1, const float* __restrict__ b1,
                 const float* __restrict__ w2, const float* __restrict__ b2,
                 const float* __restrict__ w3, const float* __restrict__ b3,
                 const float* __restrict__ lnw, const float* __restrict__ lnb,
                 int E) {
    extern __shared__ __align__(16) char dsm[];
    uint32_t dbase = smem_u32(dsm);
    uint32_t w1b = dbase;
    uint32_t w2b = w1b + WPLANE;

    __shared__ __align__(8) float w0s[192], b0s[64], b1s[64], b2s[64], w3s[64];
    __shared__ __align__(8) float lnws[192], lnbs[192];
    __shared__ float b3s;

    int tid = threadIdx.x;
    int warp = tid >> 5, lane = tid & 31;
    int qrow = lane >> 2, qc = lane & 3;

    // ---- one-time prologue: weights -> interleaved hi/lo f16x2 planes ----
    {
        const float2* w1v = (const float2*)w1;
        const float2* w2v = (const float2*)w2;
        for (int q = tid; q < 2048; q += TB) {
            int row = q >> 5, p = q & 31;
            int sp = p >> 3, i = p & 7;
            int v = (i < 4) ? (2 * i) : (2 * (i - 4) + 1);
            uint32_t base = (uint32_t)row * WRS + (uint32_t)(sp * 4 + (v >> 1)) * 16u;
            uint32_t hioff = base + (uint32_t)(v & 1) * 4u;
            uint32_t looff = hioff + 8u;
            float2 a = w1v[q];
            uint32_t hi, lo;
            split2(a.x, a.y, hi, lo);
            sts_b32(w1b + hioff, hi);
            sts_b32(w1b + looff, lo);
            float2 c = w2v[q];
            split2(c.x, c.y, hi, lo);
            sts_b32(w2b + hioff, hi);
            sts_b32(w2b + looff, lo);
        }
    }
    for (int i = tid; i < 192; i += TB) { w0s[i] = w0[i]; lnws[i] = lnw[i]; lnbs[i] = lnb[i]; }
    if (tid < 64) { b0s[tid] = b0[tid]; b1s[tid] = b1[tid]; b2s[tid] = b2[tid]; w3s[tid] = w3[tid]; }
    if (tid == 0) b3s = b3[0];
    __syncthreads();

    // ---- persistent per-warp loop over 32-edge chunks ----
    int nchunks = (E + 31) >> 5;
    int gw = blockIdx.x * (TB / 32) + warp;
    int wstride = gridDim.x * (TB / 32);

    for (int ch = gw; ch < nchunks; ch += wstride) {
        int e = ch * 32 + lane;
        bool active = (e < E);
        int eidx = active ? e : (E - 1);
        int src = ei[eidx];
        int dst = ei[E + eidx];
        float xsd = x_s[src * 2 + 1];
        float xsc = x_t[dst * 2 + 1];
        float att = ea[eidx];

        if (active) g_xy[e] = make_float2(xsd, xsc);

        // shuffle inputs to fragment rows: j=2*mt+half -> row 16*mt+8*half+qrow
        float xs4[4], xc4[4], at4[4];
#pragma unroll
        for (int j = 0; j < 4; j++) {
            int R = 16 * (j >> 1) + 8 * (j & 1) + qrow;
            xs4[j] = __shfl_sync(0xffffffffu, xsd, R);
            xc4[j] = __shfl_sync(0xffffffffu, xsc, R);
            at4[j] = __shfl_sync(0xffffffffu, att, R);
        }

        // layer0 (3->64) directly in fragment layout + LeakyReLU
        float acc[2][8][4];
#pragma unroll
        for (int mt = 0; mt < 2; mt++) {
#pragma unroll
            for (int n = 0; n < 8; n++) {
                int c0 = 8 * n + 2 * qc;
#pragma unroll
                for (int half = 0; half < 2; half++) {
                    int j = 2 * mt + half;
#pragma unroll
                    for (int cc = 0; cc < 2; cc++) {
                        int c = c0 + cc;
                        float t = w0s[c * 3] * xs4[j] + w0s[c * 3 + 1] * xc4[j]
                                + w0s[c * 3 + 2] * at4[j] + b0s[c];
                        acc[mt][n][2 * half + cc] = t > 0.f ? t : SLOPE * t;
                    }
                }
            }
        }
        frag_ln(acc, lnws, lnbs, lane);

        uint32_t Ah[2][4][4], Al[2][4][4];
        frags_from_acc(acc, Ah, Al);

        // ---- layer 1 ----
        mma_frags(acc, Ah, Al, w1b, b1s, lane);
        frag_postln(acc, lnws + 64, lnbs + 64, lane);
        frags_from_acc(acc, Ah, Al);

        // ---- layer 2 ----
        mma_frags(acc, Ah, Al, w2b, b2s, lane);
        frag_postln(acc, lnws + 128, lnbs + 128, lane);

        // ---- final dot + butterfly reduce + scatter ----
        float p[4] = {0.f, 0.f, 0.f, 0.f};
#pragma unroll
        for (int mt = 0; mt < 2; mt++) {
#pragma unroll
            for (int n = 0; n < 8; n++) {
                int c0 = 8 * n + 2 * qc;
                float wa = w3s[c0], wb = w3s[c0 + 1];
                p[2 * mt]     += acc[mt][n][0] * wa + acc[mt][n][1] * wb;
                p[2 * mt + 1] += acc[mt][n][2] * wa + acc[mt][n][3] * wb;
            }
        }
#pragma unroll
        for (int j = 0; j < 4; j++) {
            p[j] += __shfl_xor_sync(0xffffffffu, p[j], 1);
            p[j] += __shfl_xor_sync(0xffffffffu, p[j], 2);
        }
        int jw = qc;                                   // lane outputs row-group jw
        int R = 16 * (jw >> 1) + 8 * (jw & 1) + qrow;  // row within warp tile
        float yv = fmaxf(p[2 * (jw >> 1) + (jw & 1)] + b3s, 0.f);
        int ew = ch * 32 + R;
        int src_w = __shfl_sync(0xffffffffu, src, R);
        int dst_w = __shfl_sync(0xffffffffu, dst, R);
        if (ew < E) {
            g_y[ew] = yv;
            atomicAdd(&g_sum_s[src_w], yv);
            atomicAdd(&g_sum_t[dst_w], yv);
        }
    }
}

// ---------------------------------------------------------------------------
__global__ __launch_bounds__(256)
void coef_kernel(const int* __restrict__ ei,
                 const float* __restrict__ fw1, const float* __restrict__ fb1,
                 const float* __restrict__ flnw, const float* __restrict__ flnb,
                 const float* __restrict__ fw2, const float* __restrict__ fb2,
                 float* __restrict__ out, int E) {
    __shared__ float fw1s[128], fb1s[32], flnws[32], flnbs[32], fw2s[32];
    __shared__ float fb2s;
    int tid = threadIdx.x;
    if (tid < 128) fw1s[tid] = fw1[tid];
    if (tid < 32) {
        fb1s[tid] = fb1[tid];
        flnws[tid] = flnw[tid];
        flnbs[tid] = flnb[tid];
        fw2s[tid] = fw2[tid];
    }
    if (tid == 0) fb2s = fb2[0];
    __syncthreads();

    int e = blockIdx.x * blockDim.x + tid;
    if (e >= E) return;

    int src = ei[e];
    int dst = ei[E + e];
    float2 xy = g_xy[e];
    float xsd = xy.x;
    float xsc = xy.y;
    float ysi = g_sum_s[src];
    float ysj = g_sum_t[dst];

    float h[32];
#pragma unroll
    for (int j = 0; j < 32; j++) {
        float t = fw1s[j * 4] * xsd + fw1s[j * 4 + 1] * ysi +
                  fw1s[j * 4 + 2] * xsc + fw1s[j * 4 + 3] * ysj + fb1s[j];
        h[j] = fmaxf(t, 0.f);
    }
    float s = 0.f;
#pragma unroll
    for (int k = 0; k < 32; k++) s += h[k];
    float m = s * (1.0f / 32.0f);
    float v = 0.f;
#pragma unroll
    for (int k = 0; k < 32; k++) { float d = h[k] - m; v += d * d; }
    v *= (1.0f / 32.0f);
    float inv = rsqrtf(v + EPSLN);

    float acc = fb2s;
#pragma unroll
    for (int k = 0; k < 32; k++) {
        float hn = (h[k] - m) * inv * flnws[k] + flnbs[k];
        acc += fw2s[k] * hn;
    }
    acc = fmaxf(acc, 0.f);
    out[e] = g_y[e] * acc;
}

// ---------------------------------------------------------------------------
extern "C" void kernel_launch(void* const* d_in, const int* in_sizes, int n_in,
                              void* d_out, int out_size) {
    const float* x_s  = (const float*)d_in[0];
    const float* x_t  = (const float*)d_in[1];
    const int*   ei   = (const int*)d_in[2];
    const float* ea   = (const float*)d_in[3];
    const float* w0   = (const float*)d_in[4];
    const float* b0   = (const float*)d_in[5];
    const float* w1   = (const float*)d_in[6];
    const float* b1   = (const float*)d_in[7];
    const float* w2   = (const float*)d_in[8];
    const float* b2   = (const float*)d_in[9];
    const float* w3   = (const float*)d_in[10];
    const float* b3   = (const float*)d_in[11];
    const float* lnw  = (const float*)d_in[12];
    const float* lnb  = (const float*)d_in[13];
    const float* fw1  = (const float*)d_in[14];
    const float* fb1  = (const float*)d_in[15];
    const float* flnw = (const float*)d_in[16];
    const float* flnb = (const float*)d_in[17];
    const float* fw2  = (const float*)d_in[18];
    const float* fb2  = (const float*)d_in[19];

    int E  = in_sizes[3];
    int NS = in_sizes[0] / 2;
    int NT = in_sizes[1] / 2;

    int nmax = NS > NT ? NS : NT;
    zero_kernel<<<(nmax + 255) / 256, 256>>>(NS, NT);

    // two dummies so ncu's capture (global launch index 3) lands on edge_kernel
    dummy_kernel<<<1, 32>>>();
    dummy_kernel<<<1, 32>>>();

    cudaFuncSetAttribute(edge_kernel, cudaFuncAttributeMaxDynamicSharedMemorySize, DYN_SMEM);

    int ncta = (E + TB - 1) / TB;
    if (ncta > NCTA) ncta = NCTA;
    edge_kernel<<<ncta, TB, DYN_SMEM>>>(
        x_s, x_t, ei, ea, w0, b0, w1, b1, w2, b2, w3, b3, lnw, lnb, E);

    coef_kernel<<<(E + 255) / 256, 256>>>(
        ei, fw1, fb1, flnw, flnb, fw2, fb2, (float*)d_out, E);
}